// round 7
// baseline (speedup 1.0000x reference)
#include <cuda_runtime.h>
#include <cstdint>

#define V_TOT  200000
#define KNN    96
#define NSEG   4
#define SEGSZ  50000
#define NBUCKET (NSEG * 65536)

// ---------------- scratch (device globals; no allocation allowed) ----------------
__device__ int d_order[V_TOT];
__device__ unsigned long long d_tmp[V_TOT];
__device__ int d_hist[NBUCKET];
__device__ int d_cnt[NBUCKET];
__device__ int d_assign[V_TOT];     // per-vertex: local index of its cluster centre
__device__ int d_crank[V_TOT];      // per centre vertex (global idx): local rank
__device__ int d_sellocal[V_TOT];   // per segment: compacted centre vertex ids
__device__ int d_counts[NSEG];

// ---------------- sort: bucket by uniform hier, then tiny per-bucket sorts -------

__device__ __forceinline__ unsigned bucket_of(float u, int seg) {
    unsigned b16 = (unsigned)(u * 65536.0f);
    if (b16 > 65535u) b16 = 65535u;
    // ascending bucket == descending hier, segment-major
    return (unsigned)seg * 65536u + (65535u - b16);
}

__global__ void k_hist(const float* __restrict__ hier) {
    int i = blockIdx.x * blockDim.x + threadIdx.x;
    if (i >= V_TOT) return;
    atomicAdd(&d_hist[bucket_of(hier[i], i / SEGSZ)], 1);
}

__global__ void k_scan() {
    __shared__ int ssum[1024];
    int t = threadIdx.x;
    int base = t * 256;
    int s = 0;
#pragma unroll 8
    for (int k = 0; k < 256; k++) s += d_hist[base + k];
    ssum[t] = s;
    __syncthreads();
    for (int off = 1; off < 1024; off <<= 1) {
        int v = (t >= off) ? ssum[t - off] : 0;
        __syncthreads();
        ssum[t] += v;
        __syncthreads();
    }
    int run = (t == 0) ? 0 : ssum[t - 1];
    for (int k = 0; k < 256; k++) {
        int h = d_hist[base + k];
        d_hist[base + k] = run;
        run += h;
    }
}

__global__ void k_scatter(const float* __restrict__ hier) {
    int i = blockIdx.x * blockDim.x + threadIdx.x;
    if (i >= V_TOT) return;
    float u = hier[i];
    unsigned hb  = __float_as_uint(u);          // u in [0,1): bits < 0x3F800000
    unsigned inv = 0x3FFFFFFFu - hb;            // ascending inv == descending u
    unsigned b = bucket_of(u, i / SEGSZ);
    int pos = d_hist[b] + atomicAdd(&d_cnt[b], 1);
    d_tmp[pos] = ((unsigned long long)inv << 18) | (unsigned)i;  // idx < 2^18
}

__global__ void k_bsort() {
    int b = blockIdx.x * blockDim.x + threadIdx.x;
    if (b >= NBUCKET) return;
    int n = d_cnt[b];
    if (n == 0) return;
    int s = d_hist[b];
    for (int k = 1; k < n; k++) {
        unsigned long long key = d_tmp[s + k];
        int j = k - 1;
        while (j >= 0 && d_tmp[s + j] > key) { d_tmp[s + j + 1] = d_tmp[s + j]; j--; }
        d_tmp[s + j + 1] = key;
    }
    for (int k = 0; k < n; k++) d_order[s + k] = (int)(d_tmp[s + k] & 0x3FFFFull);
}

// ---------------- greedy: ONE WARP per segment, 2-deep cross-chunk prefetch ------
// Pipeline: while processing chunk i (rows already in stage[buf]), chunk i+1's
// candidate rows are speculatively prefetched into stage[buf^1]. The speculative
// ballot uses the PRE-chunk-i assign state — a superset of chunk i+1's true
// candidate set (assign is monotone), and every candidate is re-checked at
// processing time, so stale prefetches are merely unused bytes.

__device__ __forceinline__ void cpa16(void* sm, const void* g) {
    unsigned s = (unsigned)__cvta_generic_to_shared(sm);
    asm volatile("cp.async.cg.shared.global [%0], [%1], 16;\n" :: "r"(s), "l"(g));
}
__device__ __forceinline__ void cpa_commit() {
    asm volatile("cp.async.commit_group;\n");
}
__device__ __forceinline__ void cpa_wait1() {
    asm volatile("cp.async.wait_group 1;\n" ::: "memory");
}

__global__ void __launch_bounds__(32, 1) k_greedy(const int* __restrict__ neighs) {
    extern __shared__ int sh[];
    int* assign = sh;                     // SEGSZ ints (195 KB)
    int* stage0 = sh + SEGSZ;             // double-buffered neighbour rows
    int* stage1 = sh + SEGSZ + 32 * KNN;  // 2 * 12 KB

    const int seg  = blockIdx.x;
    const int base = seg * SEGSZ;
    const int lane = threadIdx.x;

    for (int i = lane; i < SEGSZ; i += 32) assign[i] = -1;
    __syncwarp();

    int ncent = 0;                        // uniform across lanes

    // ---- prologue: chunk 0 (full) — ballot + prefetch into stage0
    int o = d_order[base + lane];
    unsigned m_cur = __ballot_sync(0xffffffffu, assign[o - base] < 0);  // = ~0
    {
        unsigned mm = m_cur;
        while (mm) {
            int j = __ffs(mm) - 1; mm &= mm - 1;
            int oc = __shfl_sync(0xffffffffu, o, j);
            if (lane < 24)
                cpa16(&stage0[j * KNN + lane * 4],
                      neighs + (size_t)(unsigned)oc * KNN + lane * 4);
        }
        cpa_commit();                     // group for chunk 0
    }

    int* stages[2] = { stage0, stage1 };
    int buf = 0;

    for (int p = 0; p < SEGSZ; p += 32) {
        // ---- speculative scan + prefetch of chunk p+32 into the other buffer
        int nxt = p + 32 + lane;
        bool v_next = nxt < SEGSZ;
        int o_next = v_next ? d_order[base + nxt] : 0;
        unsigned m_next = __ballot_sync(0xffffffffu,
                                        v_next && (assign[o_next - base] < 0));
        {
            int* st = stages[buf ^ 1];
            unsigned mm = m_next;
            while (mm) {
                int j = __ffs(mm) - 1; mm &= mm - 1;
                int oc = __shfl_sync(0xffffffffu, o_next, j);
                if (lane < 24)
                    cpa16(&st[j * KNN + lane * 4],
                          neighs + (size_t)(unsigned)oc * KNN + lane * 4);
            }
            cpa_commit();                 // exactly one commit per iteration
        }

        // ---- wait for THIS chunk's rows (1 group — the one just issued — may fly)
        cpa_wait1();
        __syncwarp();

        // ---- process current chunk
        int* st = stages[buf];
        unsigned m = m_cur;
        while (m) {
            int j = __ffs(m) - 1; m &= m - 1;
            int oc = __shfl_sync(0xffffffffu, o, j);
            int ol = oc - base;
            if (assign[ol] < 0) {         // LDS broadcast re-check, lockstep
                if (lane == 0) {
                    d_sellocal[base + ncent] = oc;
                    d_crank[oc] = ncent;
                }
                ncent++;
#pragma unroll
                for (int t = 0; t < 3; t++) {
                    int nl = st[j * KNN + 32 * t + lane] - base;
                    nl = max(0, min(SEGSZ - 1, nl));   // safety clamp
                    if (assign[nl] < 0) assign[nl] = ol;
                }
                __syncwarp();             // grabs visible before next re-check
            }
        }

        o = o_next;
        m_cur = m_next;
        buf ^= 1;
    }

    __syncwarp();
    for (int i = lane; i < SEGSZ; i += 32) d_assign[base + i] = assign[i];
    if (lane == 0) d_counts[seg] = ncent;
}

// ---------------- finalize: sel | rs | ggather, written as FLOAT32 ----------------

__global__ void k_final(float* __restrict__ out) {
    __shared__ int off[NSEG + 1];
    if (threadIdx.x == 0) {
        off[0] = 0;
        for (int s = 0; s < NSEG; s++) off[s + 1] = off[s] + d_counts[s];
    }
    __syncthreads();
    int i = blockIdx.x * blockDim.x + threadIdx.x;
    if (i < V_TOT) {
        int seg = i / SEGSZ;
        int a   = d_assign[i];                         // local centre index
        out[V_TOT + NSEG + 1 + i] =
            (float)(off[seg] + d_crank[seg * SEGSZ + a]);            // ggather
        int selv = -1;
#pragma unroll
        for (int s = 0; s < NSEG; s++)
            if (i >= off[s] && i < off[s + 1])
                selv = d_sellocal[s * SEGSZ + (i - off[s])];
        out[i] = (float)selv;                          // sel (padded -1.0f)
    }
    if (i <= NSEG) out[V_TOT + i] = (float)off[i];     // rs
}

// ---------------- launch -----------------------------------------------------------

extern "C" void kernel_launch(void* const* d_in, const int* in_sizes, int n_in,
                              void* d_out, int out_size) {
    // Bind inputs by SIZE (robust to metadata ordering):
    //   neighs: 19,200,000 int32 | hier: 200,000 f32 | row_splits: 5 int32 (constants)
    const int*   neighs = nullptr;
    const float* hier   = nullptr;
    for (int i = 0; i < n_in; i++) {
        if (in_sizes[i] == V_TOT * KNN)      neighs = (const int*)d_in[i];
        else if (in_sizes[i] == V_TOT)       hier   = (const float*)d_in[i];
    }
    float* out = (float*)d_out;

    size_t smem = (size_t)SEGSZ * 4 + (size_t)2 * 32 * KNN * 4;   // 224576 B
    cudaFuncSetAttribute(k_greedy, cudaFuncAttributeMaxDynamicSharedMemorySize, (int)smem);

    void* hist_ptr = nullptr; void* cnt_ptr = nullptr;
    cudaGetSymbolAddress(&hist_ptr, d_hist);
    cudaGetSymbolAddress(&cnt_ptr,  d_cnt);
    cudaMemsetAsync(hist_ptr, 0, NBUCKET * sizeof(int));
    cudaMemsetAsync(cnt_ptr,  0, NBUCKET * sizeof(int));

    k_hist   <<<(V_TOT + 255) / 256, 256>>>(hier);
    k_scan   <<<1, 1024>>>();
    k_scatter<<<(V_TOT + 255) / 256, 256>>>(hier);
    k_bsort  <<<NBUCKET / 256, 256>>>();
    k_greedy <<<NSEG, 32, smem>>>(neighs);
    k_final  <<<(V_TOT + 255) / 256, 256>>>(out);
}

// round 8
// speedup vs baseline: 1.0723x; 1.0723x over previous
#include <cuda_runtime.h>
#include <cstdint>

#define V_TOT  200000
#define KNN    96
#define NSEG   4
#define SEGSZ  50000
#define NBUCKET (NSEG * 65536)
#define NEDGE  (V_TOT * KNN)
#define FULL_ROUNDS 4

// ---------------- scratch (device globals; no allocation allowed) ----------------
__device__ int d_order[V_TOT];                 // rank -> vertex
__device__ int d_rank[V_TOT];                  // vertex -> rank (priority, lower = earlier)
__device__ unsigned long long d_tmp[V_TOT];
__device__ int d_hist[NBUCKET];
__device__ int d_cnt[NBUCKET];
__device__ int d_state[V_TOT];                 // 0 undecided, 1 centre, 2 dead
__device__ int d_claim[V_TOT];
__device__ int d_amin[V_TOT];                  // min rank of grabbing centre
__device__ int d_front[V_TOT];
__device__ int d_front2[V_TOT];
__device__ int d_pref[V_TOT + 1];              // exclusive prefix of centre flags over positions

// ---------------- sort: bucket by uniform hier, then tiny per-bucket sorts -------

__device__ __forceinline__ unsigned bucket_of(float u, int seg) {
    unsigned b16 = (unsigned)(u * 65536.0f);
    if (b16 > 65535u) b16 = 65535u;
    return (unsigned)seg * 65536u + (65535u - b16);   // segment-major, hier descending
}

__global__ void k_hist(const float* __restrict__ hier) {
    int i = blockIdx.x * blockDim.x + threadIdx.x;
    if (i >= V_TOT) return;
    atomicAdd(&d_hist[bucket_of(hier[i], i / SEGSZ)], 1);
}

__global__ void k_scan() {
    __shared__ int ssum[1024];
    int t = threadIdx.x;
    int base = t * 256;
    int s = 0;
#pragma unroll 8
    for (int k = 0; k < 256; k++) s += d_hist[base + k];
    ssum[t] = s;
    __syncthreads();
    for (int off = 1; off < 1024; off <<= 1) {
        int v = (t >= off) ? ssum[t - off] : 0;
        __syncthreads();
        ssum[t] += v;
        __syncthreads();
    }
    int run = (t == 0) ? 0 : ssum[t - 1];
    for (int k = 0; k < 256; k++) {
        int h = d_hist[base + k];
        d_hist[base + k] = run;
        run += h;
    }
}

__global__ void k_scatter(const float* __restrict__ hier) {
    int i = blockIdx.x * blockDim.x + threadIdx.x;
    if (i >= V_TOT) return;
    float u = hier[i];
    unsigned hb  = __float_as_uint(u);
    unsigned inv = 0x3FFFFFFFu - hb;              // ascending inv == descending hier
    unsigned b = bucket_of(u, i / SEGSZ);
    int pos = d_hist[b] + atomicAdd(&d_cnt[b], 1);
    d_tmp[pos] = ((unsigned long long)inv << 18) | (unsigned)i;   // idx < 2^18
}

__global__ void k_bsort() {
    int b = blockIdx.x * blockDim.x + threadIdx.x;
    if (b >= NBUCKET) return;
    int n = d_cnt[b];
    if (n == 0) return;
    int s = d_hist[b];
    for (int k = 1; k < n; k++) {
        unsigned long long key = d_tmp[s + k];
        int j = k - 1;
        while (j >= 0 && d_tmp[s + j] > key) { d_tmp[s + j + 1] = d_tmp[s + j]; j--; }
        d_tmp[s + j + 1] = key;
    }
    for (int k = 0; k < n; k++) {
        int v = (int)(d_tmp[s + k] & 0x3FFFFull);
        d_order[s + k] = v;
        d_rank[v] = s + k;
    }
}

// ---------------- parallel greedy rounds ------------------------------------------
// v is centre <=> no centre u with rank(u) < rank(v) and v in nb(u).
// Round: undecided u writes rank(u) into claim[nb(u)] (self-edge included);
// v confirms centre iff claim[v]==rank[v]; new centres dead-mark later-ranked nb.

__global__ void k_claim(const int* __restrict__ neighs) {
    int idx = blockIdx.x * blockDim.x + threadIdx.x;
    if (idx >= NEDGE) return;
    int u = idx / KNN;
    if (d_state[u] != 0) return;
    atomicMin(&d_claim[neighs[idx]], d_rank[u]);
}

__global__ void k_confirm(const int* __restrict__ neighs) {
    int v = blockIdx.x * blockDim.x + threadIdx.x;
    if (v >= V_TOT) return;
    if (d_state[v] != 0) return;
    int c  = d_claim[v];
    d_claim[v] = 0x7FFFFFFF;            // reset for next round
    int rv = d_rank[v];
    if (c == rv) {                      // no earlier live grabber -> centre
        d_state[v] = 1;
        const int* row = neighs + (size_t)v * KNN;
#pragma unroll 8
        for (int e = 0; e < KNN; e++) {
            int w = row[e];
            if (d_rank[w] > rv) d_state[w] = 2;   // provably non-centre
        }
    }
}

// per-segment finisher: loops CTA-local rounds until segment converges.
// Segments are closed under nb(), so no cross-CTA interaction.
__global__ void __launch_bounds__(1024, 1) k_finish(const int* __restrict__ neighs) {
    __shared__ int s_cnt;
    const int seg  = blockIdx.x;
    const int base = seg * SEGSZ;
    const int tid  = threadIdx.x;

    if (tid == 0) s_cnt = 0;
    __syncthreads();
    for (int v = base + tid; v < base + SEGSZ; v += 1024)
        if (d_state[v] == 0) d_front[base + atomicAdd(&s_cnt, 1)] = v;
    __syncthreads();
    int cnt = s_cnt;

    int* fa = d_front;
    int* fb = d_front2;
    while (cnt > 0) {
        // claim phase
        for (int k = tid; k < cnt; k += 1024) {
            int u  = fa[base + k];
            int ru = d_rank[u];
            const int* row = neighs + (size_t)u * KNN;
#pragma unroll 8
            for (int e = 0; e < KNN; e++) atomicMin(&d_claim[row[e]], ru);
        }
        __syncthreads();
        // confirm + dead-mark phase
        for (int k = tid; k < cnt; k += 1024) {
            int v = fa[base + k];
            int c = d_claim[v];
            d_claim[v] = 0x7FFFFFFF;
            int rv = d_rank[v];
            if (c == rv) {
                d_state[v] = 1;
                const int* row = neighs + (size_t)v * KNN;
#pragma unroll 8
                for (int e = 0; e < KNN; e++) {
                    int w = row[e];
                    if (d_rank[w] > rv) d_state[w] = 2;
                }
            }
        }
        __syncthreads();
        if (tid == 0) s_cnt = 0;
        __syncthreads();
        for (int k = tid; k < cnt; k += 1024) {
            int v = fa[base + k];
            if (d_state[v] == 0) fb[base + atomicAdd(&s_cnt, 1)] = v;
        }
        __syncthreads();
        cnt = s_cnt;                    // min-rank frontier vertex always confirms -> progress
        int* t = fa; fa = fb; fb = t;
        __syncthreads();
    }
}

// assignment: amin[w] = min rank over centres u with w in nb(u)
__global__ void k_amin(const int* __restrict__ neighs) {
    int idx = blockIdx.x * blockDim.x + threadIdx.x;
    if (idx >= NEDGE) return;
    int u = idx / KNN;
    if (d_state[u] != 1) return;
    atomicMin(&d_amin[neighs[idx]], d_rank[u]);
}

// exclusive prefix of centre flags over order positions (one CTA)
__global__ void k_cscan() {
    __shared__ int ssum[1024];
    const int CH = (V_TOT + 1023) / 1024;   // 196
    int t  = threadIdx.x;
    int lo = t * CH;
    int hi = min(lo + CH, V_TOT);
    int s = 0;
    for (int p = lo; p < hi; p++) s += (d_state[d_order[p]] == 1);
    ssum[t] = s;
    __syncthreads();
    for (int off = 1; off < 1024; off <<= 1) {
        int v = (t >= off) ? ssum[t - off] : 0;
        __syncthreads();
        ssum[t] += v;
        __syncthreads();
    }
    int run = (t == 0) ? 0 : ssum[t - 1];
    for (int p = lo; p < hi; p++) {
        int f = (d_state[d_order[p]] == 1);
        d_pref[p] = run;
        run += f;
    }
    if (t == 1023) d_pref[V_TOT] = run;     // total centres
}

__global__ void k_prepad(float* __restrict__ out) {
    int i = blockIdx.x * blockDim.x + threadIdx.x;
    if (i < V_TOT) out[i] = -1.0f;
}

__global__ void k_final(float* __restrict__ out) {
    int i = blockIdx.x * blockDim.x + threadIdx.x;
    if (i < V_TOT) {
        int v = d_order[i];
        if (d_state[v] == 1) out[d_pref[i]] = (float)v;          // sel (compacted)
        out[V_TOT + NSEG + 1 + i] = (float)d_pref[d_amin[i]];    // ggather
    }
    if (i < NSEG)  out[V_TOT + i] = (float)d_pref[i * SEGSZ];    // rs
    if (i == NSEG) out[V_TOT + NSEG] = (float)d_pref[V_TOT];
}

// ---------------- launch -----------------------------------------------------------

extern "C" void kernel_launch(void* const* d_in, const int* in_sizes, int n_in,
                              void* d_out, int out_size) {
    const int*   neighs = nullptr;
    const float* hier   = nullptr;
    for (int i = 0; i < n_in; i++) {
        if (in_sizes[i] == NEDGE)       neighs = (const int*)d_in[i];
        else if (in_sizes[i] == V_TOT)  hier   = (const float*)d_in[i];
    }
    float* out = (float*)d_out;

    void *p_hist, *p_cnt, *p_claim, *p_amin, *p_state;
    cudaGetSymbolAddress(&p_hist,  d_hist);
    cudaGetSymbolAddress(&p_cnt,   d_cnt);
    cudaGetSymbolAddress(&p_claim, d_claim);
    cudaGetSymbolAddress(&p_amin,  d_amin);
    cudaGetSymbolAddress(&p_state, d_state);
    cudaMemsetAsync(p_hist,  0,    NBUCKET * sizeof(int));
    cudaMemsetAsync(p_cnt,   0,    NBUCKET * sizeof(int));
    cudaMemsetAsync(p_claim, 0x7F, V_TOT * sizeof(int));   // 0x7F7F7F7F > any rank
    cudaMemsetAsync(p_amin,  0x7F, V_TOT * sizeof(int));
    cudaMemsetAsync(p_state, 0,    V_TOT * sizeof(int));

    k_hist   <<<(V_TOT + 255) / 256, 256>>>(hier);
    k_scan   <<<1, 1024>>>();
    k_scatter<<<(V_TOT + 255) / 256, 256>>>(hier);
    k_bsort  <<<NBUCKET / 256, 256>>>();

    for (int r = 0; r < FULL_ROUNDS; r++) {
        k_claim  <<<(NEDGE + 255) / 256, 256>>>(neighs);
        k_confirm<<<(V_TOT + 255) / 256, 256>>>(neighs);
    }
    k_finish <<<NSEG, 1024>>>(neighs);

    k_amin   <<<(NEDGE + 255) / 256, 256>>>(neighs);
    k_cscan  <<<1, 1024>>>();
    k_prepad <<<(V_TOT + 255) / 256, 256>>>(out);
    k_final  <<<(V_TOT + 255) / 256, 256>>>(out);
}

// round 9
// speedup vs baseline: 2.2355x; 2.0848x over previous
#include <cuda_runtime.h>
#include <cstdint>

#define V_TOT  200000
#define KNN    96
#define NSEG   4
#define SEGSZ  50000
#define NBUCKET (NSEG * 65536)
#define NEDGE  (V_TOT * KNN)
#define FULL_ROUNDS 4
#define NB_C   196                    // cscan blocks: 196*1024 = 200704 >= V_TOT+1

// ---------------- scratch (device globals; no allocation allowed) ----------------
__device__ int d_order[V_TOT];                 // rank -> vertex
__device__ int d_rank[V_TOT];                  // vertex -> rank (lower = earlier)
__device__ unsigned long long d_tmp[V_TOT];
__device__ int d_hist[NBUCKET];
__device__ int d_cnt[NBUCKET];
__device__ int d_state[V_TOT];                 // 0 undecided, 1 centre, 2 dead
__device__ int d_claim[V_TOT];
__device__ int d_amin[V_TOT];                  // min rank of grabbing centre
__device__ int d_front[V_TOT];
__device__ int d_front2[V_TOT];
__device__ int d_pref[V_TOT + 1];              // exclusive prefix of centre flags
__device__ int d_bsum[256];                    // hist-scan block sums
__device__ int d_csum[256];                    // cscan block sums

// ---------------- sort: bucket by uniform hier, then tiny per-bucket sorts -------

__device__ __forceinline__ unsigned bucket_of(float u, int seg) {
    unsigned b16 = (unsigned)(u * 65536.0f);
    if (b16 > 65535u) b16 = 65535u;
    return (unsigned)seg * 65536u + (65535u - b16);   // segment-major, hier desc
}

__global__ void k_hist(const float* __restrict__ hier) {
    int i = blockIdx.x * blockDim.x + threadIdx.x;
    if (i >= V_TOT) return;
    atomicAdd(&d_hist[bucket_of(hier[i], i / SEGSZ)], 1);
}

// ---- full-chip 3-phase exclusive scan of d_hist[262144] (256 blocks x 1024) ----
__global__ void k_scan1() {
    __shared__ int s[1024];
    int t = threadIdx.x;
    s[t] = d_hist[blockIdx.x * 1024 + t];
    __syncthreads();
    for (int off = 512; off > 0; off >>= 1) {
        if (t < off) s[t] += s[t + off];
        __syncthreads();
    }
    if (t == 0) d_bsum[blockIdx.x] = s[0];
}
__global__ void k_scan2() {                    // inclusive scan of 256 block sums
    __shared__ int s[256];
    int t = threadIdx.x;
    s[t] = d_bsum[t];
    __syncthreads();
    for (int off = 1; off < 256; off <<= 1) {
        int v = (t >= off) ? s[t - off] : 0;
        __syncthreads();
        s[t] += v;
        __syncthreads();
    }
    d_bsum[t] = s[t];
}
__global__ void k_scan3() {
    __shared__ int s[1024];
    int t = threadIdx.x, b = blockIdx.x;
    int x = d_hist[b * 1024 + t];
    s[t] = x;
    __syncthreads();
    for (int off = 1; off < 1024; off <<= 1) {
        int v = (t >= off) ? s[t - off] : 0;
        __syncthreads();
        s[t] += v;
        __syncthreads();
    }
    int base = (b == 0) ? 0 : d_bsum[b - 1];
    d_hist[b * 1024 + t] = base + s[t] - x;    // exclusive
}

__global__ void k_scatter(const float* __restrict__ hier) {
    int i = blockIdx.x * blockDim.x + threadIdx.x;
    if (i >= V_TOT) return;
    float u = hier[i];
    unsigned hb  = __float_as_uint(u);
    unsigned inv = 0x3FFFFFFFu - hb;              // ascending inv == descending hier
    unsigned b = bucket_of(u, i / SEGSZ);
    int pos = d_hist[b] + atomicAdd(&d_cnt[b], 1);
    d_tmp[pos] = ((unsigned long long)inv << 18) | (unsigned)i;   // idx < 2^18
}

__global__ void k_bsort() {
    int b = blockIdx.x * blockDim.x + threadIdx.x;
    if (b >= NBUCKET) return;
    int n = d_cnt[b];
    if (n == 0) return;
    int s = d_hist[b];
    for (int k = 1; k < n; k++) {
        unsigned long long key = d_tmp[s + k];
        int j = k - 1;
        while (j >= 0 && d_tmp[s + j] > key) { d_tmp[s + j + 1] = d_tmp[s + j]; j--; }
        d_tmp[s + j + 1] = key;
    }
    for (int k = 0; k < n; k++) {
        int v = (int)(d_tmp[s + k] & 0x3FFFFull);
        d_order[s + k] = v;
        d_rank[v] = s + k;
    }
}

// ---------------- parallel greedy rounds ------------------------------------------
// v is centre <=> no centre u with rank(u) < rank(v) and v in nb(u).

__global__ void k_claim(const int* __restrict__ neighs) {
    int idx = blockIdx.x * blockDim.x + threadIdx.x;
    if (idx >= NEDGE) return;
    int u = idx / KNN;
    if (d_state[u] != 0) return;
    atomicMin(&d_claim[neighs[idx]], d_rank[u]);
}

__global__ void k_confirm(const int* __restrict__ neighs) {
    int v = blockIdx.x * blockDim.x + threadIdx.x;
    if (v >= V_TOT) return;
    if (d_state[v] != 0) return;
    int c  = d_claim[v];
    d_claim[v] = 0x7FFFFFFF;            // reset for next round
    int rv = d_rank[v];
    if (c == rv) {                      // no earlier live grabber -> centre
        d_state[v] = 1;
        const int* row = neighs + (size_t)v * KNN;
#pragma unroll 8
        for (int e = 0; e < KNN; e++) {
            int w = row[e];
            if (d_rank[w] > rv) d_state[w] = 2;
        }
    }
}

// per-segment finisher: CTA-local rounds until segment converges (segment-closed).
__global__ void __launch_bounds__(1024, 1) k_finish(const int* __restrict__ neighs) {
    __shared__ int s_cnt;
    const int seg  = blockIdx.x;
    const int base = seg * SEGSZ;
    const int tid  = threadIdx.x;

    if (tid == 0) s_cnt = 0;
    __syncthreads();
    for (int v = base + tid; v < base + SEGSZ; v += 1024)
        if (d_state[v] == 0) d_front[base + atomicAdd(&s_cnt, 1)] = v;
    __syncthreads();
    int cnt = s_cnt;

    int* fa = d_front;
    int* fb = d_front2;
    while (cnt > 0) {
        for (int k = tid; k < cnt; k += 1024) {
            int u  = fa[base + k];
            int ru = d_rank[u];
            const int* row = neighs + (size_t)u * KNN;
#pragma unroll 8
            for (int e = 0; e < KNN; e++) atomicMin(&d_claim[row[e]], ru);
        }
        __syncthreads();
        for (int k = tid; k < cnt; k += 1024) {
            int v = fa[base + k];
            int c = d_claim[v];
            d_claim[v] = 0x7FFFFFFF;
            int rv = d_rank[v];
            if (c == rv) {
                d_state[v] = 1;
                const int* row = neighs + (size_t)v * KNN;
#pragma unroll 8
                for (int e = 0; e < KNN; e++) {
                    int w = row[e];
                    if (d_rank[w] > rv) d_state[w] = 2;
                }
            }
        }
        __syncthreads();
        if (tid == 0) s_cnt = 0;
        __syncthreads();
        for (int k = tid; k < cnt; k += 1024) {
            int v = fa[base + k];
            if (d_state[v] == 0) fb[base + atomicAdd(&s_cnt, 1)] = v;
        }
        __syncthreads();
        cnt = s_cnt;                    // min-rank frontier vertex always confirms
        int* t = fa; fa = fb; fb = t;
        __syncthreads();
    }
}

__global__ void k_amin(const int* __restrict__ neighs) {
    int idx = blockIdx.x * blockDim.x + threadIdx.x;
    if (idx >= NEDGE) return;
    int u = idx / KNN;
    if (d_state[u] != 1) return;
    atomicMin(&d_amin[neighs[idx]], d_rank[u]);
}

// ---- full-chip 3-phase exclusive scan of centre flags over order positions -------
__device__ __forceinline__ int cflag(int p) {
    return (p < V_TOT && d_state[d_order[p]] == 1) ? 1 : 0;
}
__global__ void k_cscan1() {
    __shared__ int s[1024];
    int t = threadIdx.x;
    s[t] = cflag(blockIdx.x * 1024 + t);
    __syncthreads();
    for (int off = 512; off > 0; off >>= 1) {
        if (t < off) s[t] += s[t + off];
        __syncthreads();
    }
    if (t == 0) d_csum[blockIdx.x] = s[0];
}
__global__ void k_cscan2() {
    __shared__ int s[256];
    int t = threadIdx.x;
    s[t] = (t < NB_C) ? d_csum[t] : 0;
    __syncthreads();
    for (int off = 1; off < 256; off <<= 1) {
        int v = (t >= off) ? s[t - off] : 0;
        __syncthreads();
        s[t] += v;
        __syncthreads();
    }
    d_csum[t] = s[t];
}
__global__ void k_cscan3() {
    __shared__ int s[1024];
    int t = threadIdx.x, b = blockIdx.x;
    int p = b * 1024 + t;
    int x = cflag(p);
    s[t] = x;
    __syncthreads();
    for (int off = 1; off < 1024; off <<= 1) {
        int v = (t >= off) ? s[t - off] : 0;
        __syncthreads();
        s[t] += v;
        __syncthreads();
    }
    int base = (b == 0) ? 0 : d_csum[b - 1];
    if (p <= V_TOT) d_pref[p] = base + s[t] - x;   // exclusive; d_pref[V_TOT]=total
}

__global__ void k_prepad(float* __restrict__ out) {
    int i = blockIdx.x * blockDim.x + threadIdx.x;
    if (i < V_TOT) out[i] = -1.0f;
}

__global__ void k_final(float* __restrict__ out) {
    int i = blockIdx.x * blockDim.x + threadIdx.x;
    if (i < V_TOT) {
        int v = d_order[i];
        if (d_state[v] == 1) out[d_pref[i]] = (float)v;          // sel (compacted)
        out[V_TOT + NSEG + 1 + i] = (float)d_pref[d_amin[i]];    // ggather
    }
    if (i < NSEG)  out[V_TOT + i] = (float)d_pref[i * SEGSZ];    // rs
    if (i == NSEG) out[V_TOT + NSEG] = (float)d_pref[V_TOT];
}

// ---------------- launch -----------------------------------------------------------

extern "C" void kernel_launch(void* const* d_in, const int* in_sizes, int n_in,
                              void* d_out, int out_size) {
    const int*   neighs = nullptr;
    const float* hier   = nullptr;
    for (int i = 0; i < n_in; i++) {
        if (in_sizes[i] == NEDGE)       neighs = (const int*)d_in[i];
        else if (in_sizes[i] == V_TOT)  hier   = (const float*)d_in[i];
    }
    float* out = (float*)d_out;

    void *p_hist, *p_cnt, *p_claim, *p_amin, *p_state;
    cudaGetSymbolAddress(&p_hist,  d_hist);
    cudaGetSymbolAddress(&p_cnt,   d_cnt);
    cudaGetSymbolAddress(&p_claim, d_claim);
    cudaGetSymbolAddress(&p_amin,  d_amin);
    cudaGetSymbolAddress(&p_state, d_state);
    cudaMemsetAsync(p_hist,  0,    NBUCKET * sizeof(int));
    cudaMemsetAsync(p_cnt,   0,    NBUCKET * sizeof(int));
    cudaMemsetAsync(p_claim, 0x7F, V_TOT * sizeof(int));   // 0x7F7F7F7F > any rank
    cudaMemsetAsync(p_amin,  0x7F, V_TOT * sizeof(int));
    cudaMemsetAsync(p_state, 0,    V_TOT * sizeof(int));

    k_hist   <<<(V_TOT + 255) / 256, 256>>>(hier);
    k_scan1  <<<256, 1024>>>();
    k_scan2  <<<1, 256>>>();
    k_scan3  <<<256, 1024>>>();
    k_scatter<<<(V_TOT + 255) / 256, 256>>>(hier);
    k_bsort  <<<NBUCKET / 256, 256>>>();

    for (int r = 0; r < FULL_ROUNDS; r++) {
        k_claim  <<<(NEDGE + 255) / 256, 256>>>(neighs);
        k_confirm<<<(V_TOT + 255) / 256, 256>>>(neighs);
    }
    k_finish <<<NSEG, 1024>>>(neighs);

    k_amin   <<<(NEDGE + 255) / 256, 256>>>(neighs);
    k_cscan1 <<<NB_C, 1024>>>();
    k_cscan2 <<<1, 256>>>();
    k_cscan3 <<<NB_C, 1024>>>();
    k_prepad <<<(V_TOT + 255) / 256, 256>>>(out);
    k_final  <<<(V_TOT + 255) / 256, 256>>>(out);
}

// round 10
// speedup vs baseline: 2.5663x; 1.1480x over previous
#include <cuda_runtime.h>
#include <cstdint>

#define V_TOT  200000
#define KNN    96
#define NSEG   4
#define SEGSZ  50000
#define NBPS   16384                     // buckets per segment
#define NBUCKET (NSEG * NBPS)            // 65536
#define NEDGE  (V_TOT * KNN)
#define INF0   0x7F7F7F7F
#define NB_C   196                       // cscan blocks (196*1024 >= V_TOT+1)
#define FGRID  2048                      // frontier-round grid

// ---------------- scratch (device globals) ----------------------------------------
__device__ int d_order[V_TOT];           // rank -> vertex
__device__ int d_rank[V_TOT];            // vertex -> rank
__device__ unsigned long long d_tmp[V_TOT];
__device__ int d_hist[NBUCKET];
__device__ int d_cnt[NBUCKET];
__device__ int d_state[V_TOT];           // 0 undecided, 1 centre, 2 dead
__device__ int d_claim[V_TOT];
__device__ int d_amin[V_TOT];            // min rank of grabbing centre
__device__ int d_frontA[V_TOT];
__device__ int d_frontB[V_TOT];
__device__ int d_nf[2];                  // frontier counts (A, B)
__device__ int d_pref[V_TOT + 1];
__device__ int d_sel[V_TOT];             // compacted centre list
__device__ int d_bsum[64];
__device__ int d_csum[256];

// ---------------- sort ------------------------------------------------------------

__device__ __forceinline__ unsigned bucket_of(float u, int seg) {
    unsigned b = (unsigned)(u * 16384.0f);
    if (b > 16383u) b = 16383u;
    return (unsigned)seg * NBPS + (16383u - b);     // segment-major, hier desc
}

__global__ void k_hist(const float* __restrict__ hier) {
    int i = blockIdx.x * blockDim.x + threadIdx.x;
    if (i >= V_TOT) return;
    atomicAdd(&d_hist[bucket_of(hier[i], i / SEGSZ)], 1);
}

__global__ void k_scan1() {
    __shared__ int s[1024];
    int t = threadIdx.x;
    s[t] = d_hist[blockIdx.x * 1024 + t];
    __syncthreads();
    for (int off = 512; off > 0; off >>= 1) {
        if (t < off) s[t] += s[t + off];
        __syncthreads();
    }
    if (t == 0) d_bsum[blockIdx.x] = s[0];
}
__global__ void k_scan2() {                    // inclusive over 64 block sums
    __shared__ int s[64];
    int t = threadIdx.x;
    s[t] = d_bsum[t];
    __syncthreads();
    for (int off = 1; off < 64; off <<= 1) {
        int v = (t >= off) ? s[t - off] : 0;
        __syncthreads();
        s[t] += v;
        __syncthreads();
    }
    d_bsum[t] = s[t];
}
__global__ void k_scan3() {
    __shared__ int s[1024];
    int t = threadIdx.x, b = blockIdx.x;
    int x = d_hist[b * 1024 + t];
    s[t] = x;
    __syncthreads();
    for (int off = 1; off < 1024; off <<= 1) {
        int v = (t >= off) ? s[t - off] : 0;
        __syncthreads();
        s[t] += v;
        __syncthreads();
    }
    int base = (b == 0) ? 0 : d_bsum[b - 1];
    d_hist[b * 1024 + t] = base + s[t] - x;          // exclusive
}

__global__ void k_scatter(const float* __restrict__ hier) {
    int i = blockIdx.x * blockDim.x + threadIdx.x;
    if (i >= V_TOT) return;
    float u = hier[i];
    unsigned inv = 0x3FFFFFFFu - __float_as_uint(u); // ascending inv == descending u
    unsigned b = bucket_of(u, i / SEGSZ);
    int pos = d_hist[b] + atomicAdd(&d_cnt[b], 1);
    d_tmp[pos] = ((unsigned long long)inv << 18) | (unsigned)i;
}

__global__ void k_bsort() {
    int b = blockIdx.x * blockDim.x + threadIdx.x;
    if (b >= NBUCKET) return;
    int n = d_cnt[b];
    if (n == 0) return;
    int s = d_hist[b];
    for (int k = 1; k < n; k++) {
        unsigned long long key = d_tmp[s + k];
        int j = k - 1;
        while (j >= 0 && d_tmp[s + j] > key) { d_tmp[s + j + 1] = d_tmp[s + j]; j--; }
        d_tmp[s + j + 1] = key;
    }
    for (int k = 0; k < n; k++) {
        int v = (int)(d_tmp[s + k] & 0x3FFFFull);
        d_order[s + k] = v;
        d_rank[v] = s + k;
    }
}

// ---------------- parallel greedy ---------------------------------------------------
// v centre <=> claim[v]==rank[v] after all undecided in-neighbours claimed.
// Confirmed centre fuses amin updates + dead-marking in one row pass.

__device__ __forceinline__ void centre_row(int v, int rv, const int* __restrict__ neighs) {
    const int4* row = (const int4*)(neighs + (size_t)v * KNN);
#pragma unroll
    for (int e = 0; e < KNN / 4; e++) {
        int4 w4 = row[e];
        int w;
        w = w4.x; atomicMin(&d_amin[w], rv); if (d_rank[w] > rv) d_state[w] = 2;
        w = w4.y; atomicMin(&d_amin[w], rv); if (d_rank[w] > rv) d_state[w] = 2;
        w = w4.z; atomicMin(&d_amin[w], rv); if (d_rank[w] > rv) d_state[w] = 2;
        w = w4.w; atomicMin(&d_amin[w], rv); if (d_rank[w] > rv) d_state[w] = 2;
    }
}

__global__ void k_claim1(const int* __restrict__ neighs) {   // round 1: all undecided
    int idx = blockIdx.x * blockDim.x + threadIdx.x;
    if (idx >= NEDGE) return;
    atomicMin(&d_claim[neighs[idx]], d_rank[idx / KNN]);
}

__global__ void k_confirm1(const int* __restrict__ neighs) {
    int v = blockIdx.x * blockDim.x + threadIdx.x;
    if (v >= V_TOT) return;
    int c = d_claim[v];
    d_claim[v] = INF0;
    int rv = d_rank[v];
    if (c == rv) {
        d_state[v] = 1;
        centre_row(v, rv, neighs);
    } else if (d_state[v] == 0) {
        d_frontA[atomicAdd(&d_nf[0], 1)] = v;        // may be dead-marked later: ok
    }
}

__global__ void k_claim_f(const int* __restrict__ neighs,
                          const int* __restrict__ front, int srcSel) {
    if (blockIdx.x == 0 && threadIdx.x == 0) d_nf[srcSel ^ 1] = 0;
    int n = d_nf[srcSel] * KNN;
    int stride = gridDim.x * blockDim.x;
    for (int idx = blockIdx.x * blockDim.x + threadIdx.x; idx < n; idx += stride) {
        int u = front[idx / KNN];
        if (d_state[u] != 0) continue;
        atomicMin(&d_claim[neighs[(size_t)u * KNN + idx % KNN]], d_rank[u]);
    }
}

__global__ void k_confirm_f(const int* __restrict__ neighs,
                            const int* __restrict__ front,
                            int* __restrict__ frontNext, int srcSel) {
    int n = d_nf[srcSel];
    int stride = gridDim.x * blockDim.x;
    for (int k = blockIdx.x * blockDim.x + threadIdx.x; k < n; k += stride) {
        int v = front[k];
        if (d_state[v] != 0) continue;
        int c = d_claim[v];
        d_claim[v] = INF0;
        int rv = d_rank[v];
        if (c == rv) {
            d_state[v] = 1;
            centre_row(v, rv, neighs);
        } else if (d_state[v] == 0) {
            frontNext[atomicAdd(&d_nf[srcSel ^ 1], 1)] = v;
        }
    }
}

// per-segment finisher: guaranteed convergence (segments closed under nb()).
__global__ void __launch_bounds__(1024, 1) k_finish(const int* __restrict__ neighs) {
    __shared__ int s_cnt;
    const int seg  = blockIdx.x;
    const int base = seg * SEGSZ;
    const int tid  = threadIdx.x;

    if (tid == 0) s_cnt = 0;
    __syncthreads();
    for (int v = base + tid; v < base + SEGSZ; v += 1024)
        if (d_state[v] == 0) d_frontA[base + atomicAdd(&s_cnt, 1)] = v;
    __syncthreads();
    int cnt = s_cnt;

    int* fa = d_frontA;
    int* fb = d_frontB;
    while (cnt > 0) {
        for (int k = tid; k < cnt; k += 1024) {
            int u  = fa[base + k];
            int ru = d_rank[u];
            const int* row = neighs + (size_t)u * KNN;
#pragma unroll 8
            for (int e = 0; e < KNN; e++) atomicMin(&d_claim[row[e]], ru);
        }
        __syncthreads();
        for (int k = tid; k < cnt; k += 1024) {
            int v = fa[base + k];
            int c = d_claim[v];
            d_claim[v] = INF0;
            int rv = d_rank[v];
            if (c == rv) {
                d_state[v] = 1;
                centre_row(v, rv, neighs);
            }
        }
        __syncthreads();
        if (tid == 0) s_cnt = 0;
        __syncthreads();
        for (int k = tid; k < cnt; k += 1024) {
            int v = fa[base + k];
            if (d_state[v] == 0) fb[base + atomicAdd(&s_cnt, 1)] = v;
        }
        __syncthreads();
        cnt = s_cnt;                     // min-rank frontier vertex always confirms
        int* t = fa; fa = fb; fb = t;
        __syncthreads();
    }
}

// ---- full-chip scan of centre flags over order positions + sel compaction --------
__device__ __forceinline__ int cflag(int p) {
    return (p < V_TOT && d_state[d_order[p]] == 1) ? 1 : 0;
}
__global__ void k_cscan1() {
    __shared__ int s[1024];
    int t = threadIdx.x;
    s[t] = cflag(blockIdx.x * 1024 + t);
    __syncthreads();
    for (int off = 512; off > 0; off >>= 1) {
        if (t < off) s[t] += s[t + off];
        __syncthreads();
    }
    if (t == 0) d_csum[blockIdx.x] = s[0];
}
__global__ void k_cscan2() {
    __shared__ int s[256];
    int t = threadIdx.x;
    s[t] = (t < NB_C) ? d_csum[t] : 0;
    __syncthreads();
    for (int off = 1; off < 256; off <<= 1) {
        int v = (t >= off) ? s[t - off] : 0;
        __syncthreads();
        s[t] += v;
        __syncthreads();
    }
    d_csum[t] = s[t];
}
__global__ void k_cscan3() {
    __shared__ int s[1024];
    int t = threadIdx.x, b = blockIdx.x;
    int p = b * 1024 + t;
    int x = cflag(p);
    s[t] = x;
    __syncthreads();
    for (int off = 1; off < 1024; off <<= 1) {
        int v = (t >= off) ? s[t - off] : 0;
        __syncthreads();
        s[t] += v;
        __syncthreads();
    }
    int base = (b == 0) ? 0 : d_csum[b - 1];
    int pref = base + s[t] - x;                      // exclusive
    if (p <= V_TOT) d_pref[p] = pref;
    if (x) d_sel[pref] = d_order[p];                 // compact centre list
}

__global__ void k_final(float* __restrict__ out) {
    int i = blockIdx.x * blockDim.x + threadIdx.x;
    if (i < V_TOT) {
        int total = d_pref[V_TOT];
        out[i] = (i < total) ? (float)d_sel[i] : -1.0f;          // sel
        out[V_TOT + NSEG + 1 + i] = (float)d_pref[d_amin[i]];    // ggather
    }
    if (i < NSEG)  out[V_TOT + i] = (float)d_pref[i * SEGSZ];    // rs
    if (i == NSEG) out[V_TOT + NSEG] = (float)d_pref[V_TOT];
}

// ---------------- launch -----------------------------------------------------------

extern "C" void kernel_launch(void* const* d_in, const int* in_sizes, int n_in,
                              void* d_out, int out_size) {
    const int*   neighs = nullptr;
    const float* hier   = nullptr;
    for (int i = 0; i < n_in; i++) {
        if (in_sizes[i] == NEDGE)       neighs = (const int*)d_in[i];
        else if (in_sizes[i] == V_TOT)  hier   = (const float*)d_in[i];
    }
    float* out = (float*)d_out;

    void *p_hist, *p_cnt, *p_claim, *p_amin, *p_state, *p_nf, *p_fA, *p_fB;
    cudaGetSymbolAddress(&p_hist,  d_hist);
    cudaGetSymbolAddress(&p_cnt,   d_cnt);
    cudaGetSymbolAddress(&p_claim, d_claim);
    cudaGetSymbolAddress(&p_amin,  d_amin);
    cudaGetSymbolAddress(&p_state, d_state);
    cudaGetSymbolAddress(&p_nf,    d_nf);
    cudaGetSymbolAddress(&p_fA,    d_frontA);
    cudaGetSymbolAddress(&p_fB,    d_frontB);
    cudaMemsetAsync(p_hist,  0,    NBUCKET * sizeof(int));
    cudaMemsetAsync(p_cnt,   0,    NBUCKET * sizeof(int));
    cudaMemsetAsync(p_claim, 0x7F, V_TOT * sizeof(int));
    cudaMemsetAsync(p_amin,  0x7F, V_TOT * sizeof(int));
    cudaMemsetAsync(p_state, 0,    V_TOT * sizeof(int));
    cudaMemsetAsync(p_nf,    0,    2 * sizeof(int));

    k_hist   <<<(V_TOT + 255) / 256, 256>>>(hier);
    k_scan1  <<<64, 1024>>>();
    k_scan2  <<<1, 64>>>();
    k_scan3  <<<64, 1024>>>();
    k_scatter<<<(V_TOT + 255) / 256, 256>>>(hier);
    k_bsort  <<<NBUCKET / 256, 256>>>();

    k_claim1  <<<(NEDGE + 255) / 256, 256>>>(neighs);
    k_confirm1<<<(V_TOT + 255) / 256, 256>>>(neighs);     // builds frontier A (sel 0)

    int* fA = (int*)p_fA;
    int* fB = (int*)p_fB;
    // 3 frontier rounds: A->B, B->A, A->B
    k_claim_f  <<<FGRID, 256>>>(neighs, fA, 0);
    k_confirm_f<<<FGRID, 256>>>(neighs, fA, fB, 0);
    k_claim_f  <<<FGRID, 256>>>(neighs, fB, 1);
    k_confirm_f<<<FGRID, 256>>>(neighs, fB, fA, 1);
    k_claim_f  <<<FGRID, 256>>>(neighs, fA, 0);
    k_confirm_f<<<FGRID, 256>>>(neighs, fA, fB, 0);

    k_finish <<<NSEG, 1024>>>(neighs);

    k_cscan1 <<<NB_C, 1024>>>();
    k_cscan2 <<<1, 256>>>();
    k_cscan3 <<<NB_C, 1024>>>();
    k_final  <<<(V_TOT + 255) / 256, 256>>>(out);
}

// round 11
// speedup vs baseline: 3.5365x; 1.3781x over previous
#include <cuda_runtime.h>
#include <cstdint>

#define V_TOT  200000
#define KNN    96
#define NSEG   4
#define SEGSZ  50000
#define NBPS   16384
#define NBUCKET (NSEG * NBPS)            // 65536
#define NEDGE  (V_TOT * KNN)
#define INF0   0x7F7F7F7F
#define NB_C   196
#define FGRID  2048

// ---------------- scratch (device globals) ----------------------------------------
__device__ int d_order[V_TOT];
__device__ int d_rank[V_TOT];
__device__ unsigned long long d_tmp[V_TOT];
__device__ int d_hist[NBUCKET];
__device__ int d_cnt[NBUCKET];
__device__ int d_state[V_TOT];           // 0 undecided, 1 centre, 2 dead
__device__ int d_claim[V_TOT];
__device__ int d_amin[V_TOT];
__device__ int d_frontA[V_TOT];
__device__ int d_frontB[V_TOT];
__device__ int d_nf[2];
__device__ int d_pref[V_TOT + 1];
__device__ int d_sel[V_TOT];
__device__ int d_bsum[64];
__device__ int d_csum[256];

// ---------------- init: one kernel instead of six memsets --------------------------
__global__ void k_init() {
    int i = blockIdx.x * blockDim.x + threadIdx.x;
    int stride = gridDim.x * blockDim.x;
    for (int j = i; j < NBUCKET; j += stride) { d_hist[j] = 0; d_cnt[j] = 0; }
    for (int j = i; j < V_TOT; j += stride) {
        d_claim[j] = INF0; d_amin[j] = INF0; d_state[j] = 0;
    }
    if (i < 2) d_nf[i] = 0;
}

// ---------------- sort ------------------------------------------------------------

__device__ __forceinline__ unsigned bucket_of(float u, int seg) {
    unsigned b = (unsigned)(u * 16384.0f);
    if (b > 16383u) b = 16383u;
    return (unsigned)seg * NBPS + (16383u - b);     // segment-major, hier desc
}

__global__ void k_hist(const float* __restrict__ hier) {
    int i = blockIdx.x * blockDim.x + threadIdx.x;
    if (i >= V_TOT) return;
    atomicAdd(&d_hist[bucket_of(hier[i], i / SEGSZ)], 1);
}

__global__ void k_scan1() {
    __shared__ int s[1024];
    int t = threadIdx.x;
    s[t] = d_hist[blockIdx.x * 1024 + t];
    __syncthreads();
    for (int off = 512; off > 0; off >>= 1) {
        if (t < off) s[t] += s[t + off];
        __syncthreads();
    }
    if (t == 0) d_bsum[blockIdx.x] = s[0];
}
// phase 3 with fused block-sum scan (each block scans the 64 sums locally)
__global__ void k_scan3() {
    __shared__ int s[1024];
    __shared__ int s2[64];
    int t = threadIdx.x, b = blockIdx.x;
    if (t < 64) s2[t] = d_bsum[t];
    int x = d_hist[b * 1024 + t];
    s[t] = x;
    __syncthreads();
    for (int off = 1; off < 64; off <<= 1) {
        int v = (t < 64 && t >= off) ? s2[t - off] : 0;
        __syncthreads();
        if (t < 64) s2[t] += v;
        __syncthreads();
    }
    for (int off = 1; off < 1024; off <<= 1) {
        int v = (t >= off) ? s[t - off] : 0;
        __syncthreads();
        s[t] += v;
        __syncthreads();
    }
    int base = (b == 0) ? 0 : s2[b - 1];
    d_hist[b * 1024 + t] = base + s[t] - x;          // exclusive
}

__global__ void k_scatter(const float* __restrict__ hier) {
    int i = blockIdx.x * blockDim.x + threadIdx.x;
    if (i >= V_TOT) return;
    float u = hier[i];
    unsigned inv = 0x3FFFFFFFu - __float_as_uint(u);
    unsigned b = bucket_of(u, i / SEGSZ);
    int pos = d_hist[b] + atomicAdd(&d_cnt[b], 1);
    d_tmp[pos] = ((unsigned long long)inv << 18) | (unsigned)i;
}

__global__ void k_bsort() {
    int b = blockIdx.x * blockDim.x + threadIdx.x;
    if (b >= NBUCKET) return;
    int n = d_cnt[b];
    if (n == 0) return;
    int s = d_hist[b];
    for (int k = 1; k < n; k++) {
        unsigned long long key = d_tmp[s + k];
        int j = k - 1;
        while (j >= 0 && d_tmp[s + j] > key) { d_tmp[s + j + 1] = d_tmp[s + j]; j--; }
        d_tmp[s + j + 1] = key;
    }
    for (int k = 0; k < n; k++) {
        int v = (int)(d_tmp[s + k] & 0x3FFFFull);
        d_order[s + k] = v;
        d_rank[v] = s + k;
    }
}

// ---------------- parallel greedy ---------------------------------------------------

__device__ __forceinline__ void centre_row(int v, int rv, const int* __restrict__ neighs) {
    const int4* row = (const int4*)(neighs + (size_t)v * KNN);
#pragma unroll
    for (int e = 0; e < KNN / 4; e++) {
        int4 w4 = row[e];
        int w;
        w = w4.x; atomicMin(&d_amin[w], rv); if (d_rank[w] > rv) d_state[w] = 2;
        w = w4.y; atomicMin(&d_amin[w], rv); if (d_rank[w] > rv) d_state[w] = 2;
        w = w4.z; atomicMin(&d_amin[w], rv); if (d_rank[w] > rv) d_state[w] = 2;
        w = w4.w; atomicMin(&d_amin[w], rv); if (d_rank[w] > rv) d_state[w] = 2;
    }
}

__global__ void k_claim1(const int* __restrict__ neighs) {   // round 1: all undecided
    int idx = blockIdx.x * blockDim.x + threadIdx.x;
    if (idx >= NEDGE) return;
    atomicMin(&d_claim[neighs[idx]], d_rank[idx / KNN]);
}

__global__ void k_confirm1(const int* __restrict__ neighs) {
    int v = blockIdx.x * blockDim.x + threadIdx.x;
    if (v >= V_TOT) return;
    int c = d_claim[v];
    d_claim[v] = INF0;
    int rv = d_rank[v];
    if (c == rv) {
        d_state[v] = 1;
        centre_row(v, rv, neighs);
    } else if (d_state[v] == 0) {
        d_frontA[atomicAdd(&d_nf[0], 1)] = v;
    }
}

__global__ void k_claim_f(const int* __restrict__ neighs,
                          const int* __restrict__ front, int srcSel) {
    if (blockIdx.x == 0 && threadIdx.x == 0) d_nf[srcSel ^ 1] = 0;
    int n = d_nf[srcSel] * KNN;
    int stride = gridDim.x * blockDim.x;
    for (int idx = blockIdx.x * blockDim.x + threadIdx.x; idx < n; idx += stride) {
        int u = front[idx / KNN];
        if (d_state[u] != 0) continue;
        atomicMin(&d_claim[neighs[(size_t)u * KNN + idx % KNN]], d_rank[u]);
    }
}

__global__ void k_confirm_f(const int* __restrict__ neighs,
                            const int* __restrict__ front,
                            int* __restrict__ frontNext, int srcSel) {
    int n = d_nf[srcSel];
    int stride = gridDim.x * blockDim.x;
    for (int k = blockIdx.x * blockDim.x + threadIdx.x; k < n; k += stride) {
        int v = front[k];
        if (d_state[v] != 0) continue;
        int c = d_claim[v];
        d_claim[v] = INF0;
        int rv = d_rank[v];
        if (c == rv) {
            d_state[v] = 1;
            centre_row(v, rv, neighs);
        } else if (d_state[v] == 0) {
            frontNext[atomicAdd(&d_nf[srcSel ^ 1], 1)] = v;
        }
    }
}

// per-segment finisher: guaranteed convergence (segments closed under nb()).
__global__ void __launch_bounds__(1024, 1) k_finish(const int* __restrict__ neighs) {
    __shared__ int s_cnt;
    const int seg  = blockIdx.x;
    const int base = seg * SEGSZ;
    const int tid  = threadIdx.x;

    if (tid == 0) s_cnt = 0;
    __syncthreads();
    for (int v = base + tid; v < base + SEGSZ; v += 1024)
        if (d_state[v] == 0) d_frontA[base + atomicAdd(&s_cnt, 1)] = v;
    __syncthreads();
    int cnt = s_cnt;

    int* fa = d_frontA;
    int* fb = d_frontB;
    while (cnt > 0) {
        for (int k = tid; k < cnt; k += 1024) {
            int u  = fa[base + k];
            int ru = d_rank[u];
            const int* row = neighs + (size_t)u * KNN;
#pragma unroll 8
            for (int e = 0; e < KNN; e++) atomicMin(&d_claim[row[e]], ru);
        }
        __syncthreads();
        for (int k = tid; k < cnt; k += 1024) {
            int v = fa[base + k];
            int c = d_claim[v];
            d_claim[v] = INF0;
            int rv = d_rank[v];
            if (c == rv) {
                d_state[v] = 1;
                centre_row(v, rv, neighs);
            }
        }
        __syncthreads();
        if (tid == 0) s_cnt = 0;
        __syncthreads();
        for (int k = tid; k < cnt; k += 1024) {
            int v = fa[base + k];
            if (d_state[v] == 0) fb[base + atomicAdd(&s_cnt, 1)] = v;
        }
        __syncthreads();
        cnt = s_cnt;
        int* t = fa; fa = fb; fb = t;
        __syncthreads();
    }
}

// ---- full-chip scan of centre flags over order positions + sel compaction --------
__device__ __forceinline__ int cflag(int p) {
    return (p < V_TOT && d_state[d_order[p]] == 1) ? 1 : 0;
}
__global__ void k_cscan1() {
    __shared__ int s[1024];
    int t = threadIdx.x;
    s[t] = cflag(blockIdx.x * 1024 + t);
    __syncthreads();
    for (int off = 512; off > 0; off >>= 1) {
        if (t < off) s[t] += s[t + off];
        __syncthreads();
    }
    if (t == 0) d_csum[blockIdx.x] = s[0];
}
__global__ void k_cscan3() {
    __shared__ int s[1024];
    __shared__ int s2[256];
    int t = threadIdx.x, b = blockIdx.x;
    s2[t < 256 ? t : 0] = 0;          // ensure init
    __syncthreads();
    if (t < NB_C) s2[t] = d_csum[t];
    int p = b * 1024 + t;
    int x = cflag(p);
    s[t] = x;
    __syncthreads();
    for (int off = 1; off < 256; off <<= 1) {
        int v = (t < 256 && t >= off) ? s2[t - off] : 0;
        __syncthreads();
        if (t < 256) s2[t] += v;
        __syncthreads();
    }
    for (int off = 1; off < 1024; off <<= 1) {
        int v = (t >= off) ? s[t - off] : 0;
        __syncthreads();
        s[t] += v;
        __syncthreads();
    }
    int base = (b == 0) ? 0 : s2[b - 1];
    int pref = base + s[t] - x;                      // exclusive
    if (p <= V_TOT) d_pref[p] = pref;
    if (x) d_sel[pref] = d_order[p];
}

__global__ void k_final(float* __restrict__ out) {
    int i = blockIdx.x * blockDim.x + threadIdx.x;
    if (i < V_TOT) {
        int total = d_pref[V_TOT];
        out[i] = (i < total) ? (float)d_sel[i] : -1.0f;          // sel
        out[V_TOT + NSEG + 1 + i] = (float)d_pref[d_amin[i]];    // ggather
    }
    if (i < NSEG)  out[V_TOT + i] = (float)d_pref[i * SEGSZ];    // rs
    if (i == NSEG) out[V_TOT + NSEG] = (float)d_pref[V_TOT];
}

// ---------------- launch -----------------------------------------------------------

extern "C" void kernel_launch(void* const* d_in, const int* in_sizes, int n_in,
                              void* d_out, int out_size) {
    const int*   neighs = nullptr;
    const float* hier   = nullptr;
    for (int i = 0; i < n_in; i++) {
        if (in_sizes[i] == NEDGE)       neighs = (const int*)d_in[i];
        else if (in_sizes[i] == V_TOT)  hier   = (const float*)d_in[i];
    }
    float* out = (float*)d_out;

    void *p_fA, *p_fB;
    cudaGetSymbolAddress(&p_fA, d_frontA);
    cudaGetSymbolAddress(&p_fB, d_frontB);
    int* fA = (int*)p_fA;
    int* fB = (int*)p_fB;

    k_init   <<<512, 256>>>();
    k_hist   <<<(V_TOT + 255) / 256, 256>>>(hier);
    k_scan1  <<<64, 1024>>>();
    k_scan3  <<<64, 1024>>>();
    k_scatter<<<(V_TOT + 255) / 256, 256>>>(hier);
    k_bsort  <<<NBUCKET / 256, 256>>>();

    k_claim1  <<<(NEDGE + 255) / 256, 256>>>(neighs);
    k_confirm1<<<(V_TOT + 255) / 256, 256>>>(neighs);

    // 5 frontier rounds: A->B, B->A, A->B, B->A, A->B
    k_claim_f  <<<FGRID, 256>>>(neighs, fA, 0);
    k_confirm_f<<<FGRID, 256>>>(neighs, fA, fB, 0);
    k_claim_f  <<<FGRID, 256>>>(neighs, fB, 1);
    k_confirm_f<<<FGRID, 256>>>(neighs, fB, fA, 1);
    k_claim_f  <<<FGRID, 256>>>(neighs, fA, 0);
    k_confirm_f<<<FGRID, 256>>>(neighs, fA, fB, 0);
    k_claim_f  <<<FGRID, 256>>>(neighs, fB, 1);
    k_confirm_f<<<FGRID, 256>>>(neighs, fB, fA, 1);
    k_claim_f  <<<FGRID, 256>>>(neighs, fA, 0);
    k_confirm_f<<<FGRID, 256>>>(neighs, fA, fB, 0);

    k_finish <<<NSEG, 1024>>>(neighs);

    k_cscan1 <<<NB_C, 1024>>>();
    k_cscan3 <<<NB_C, 1024>>>();
    k_final  <<<(V_TOT + 255) / 256, 256>>>(out);
}